// round 9
// baseline (speedup 1.0000x reference)
#include <cuda_runtime.h>
#include <cuda_bf16.h>
#include <cstdint>

// VQ lookup via warp-level bf16 mma.sync (HMMA) + exact fp32 refinement.
//   dot(z,c) ~= zh*ch + zh*cl + zl*ch   (2-way bf16 Dekker split, 3 passes)
//   d2 = c_sq - 2*dot ; top-2 tracked ; gap < TAU -> exact fp32 re-argmin.
// R9: codebook pre-split to bf16 hi/lo ONCE (global), pairwise z split.

#define D_DIM   510
#define K_CODES 128
#define BM      128
#define KC      64           // K-chunk (elements)
#define NCH     8            // 8*64 = 512, cols 510/511 zeroed
#define TAU     0.01f
#define ST      144          // smem tile row stride BYTES (72 bf16)

// smem byte offsets
#define SM_CSQ  0                        // 128 f32
#define SM_KF   512                      // 128 i32
#define SM_BV   1024                     // 2*128 f32
#define SM_SV   2048                     // 2*128 f32
#define SM_BK   3072                     // 2*128 i32
#define SM_ZH   4096                     // 128*ST
#define SM_ZL   (SM_ZH + 128*ST)
#define SM_CH   (SM_ZL + 128*ST)
#define SM_CL   (SM_CH + 128*ST)
#define SMEM_BYTES (SM_CL + 128*ST)      // 77824

__device__ float g_csq[K_CODES];
__device__ unsigned char g_flag[131072];
__device__ __nv_bfloat16 g_cbh[K_CODES * 512];   // codebook hi, 512-padded rows
__device__ __nv_bfloat16 g_cbl[K_CODES * 512];   // codebook lo

// ---------------------------------------------------------------- prep: c_sq + cb split
__global__ void prep_kernel(const float* __restrict__ cb) {
    int k = blockIdx.x, tid = threadIdx.x;
    float s = 0.f;
    for (int d = tid; d < 512; d += 256) {
        float v = (d < D_DIM) ? cb[k * D_DIM + d] : 0.f;
        __nv_bfloat16 h = __float2bfloat16(v);
        __nv_bfloat16 l = __float2bfloat16(v - __bfloat162float(h));
        g_cbh[k * 512 + d] = h;
        g_cbl[k * 512 + d] = l;
        s = fmaf(v, v, s);
    }
    #pragma unroll
    for (int off = 16; off; off >>= 1) s += __shfl_xor_sync(0xffffffffu, s, off);
    __shared__ float red[8];
    if ((tid & 31) == 0) red[tid >> 5] = s;
    __syncthreads();
    if (tid == 0) {
        float t = 0.f;
        #pragma unroll
        for (int i = 0; i < 8; i++) t += red[i];
        g_csq[k] = t;
    }
}

// ---------------------------------------------------------------- helpers
__device__ __forceinline__ uint32_t bits2(__nv_bfloat162 v) {
    return *reinterpret_cast<uint32_t*>(&v);
}

__device__ __forceinline__ void ldm4(uint32_t* r, uint32_t addr) {
    asm volatile("ldmatrix.sync.aligned.m8n8.x4.shared.b16 {%0,%1,%2,%3}, [%4];"
                 : "=r"(r[0]), "=r"(r[1]), "=r"(r[2]), "=r"(r[3]) : "r"(addr));
}
__device__ __forceinline__ void mma16816(float* d, const uint32_t* a,
                                         const uint32_t* b) {
    asm volatile(
        "mma.sync.aligned.m16n8k16.row.col.f32.bf16.bf16.f32 "
        "{%0,%1,%2,%3}, {%4,%5,%6,%7}, {%8,%9}, {%0,%1,%2,%3};"
        : "+f"(d[0]), "+f"(d[1]), "+f"(d[2]), "+f"(d[3])
        : "r"(a[0]), "r"(a[1]), "r"(a[2]), "r"(a[3]), "r"(b[0]), "r"(b[1]));
}

__device__ __forceinline__ void merge2(float& bv, float& sv, int& bk,
                                       float obv, float osv, int obk) {
    if (obv < bv) { sv = fminf(bv, osv); bv = obv; bk = obk; }
    else          { sv = fminf(sv, obv); }
}

extern __shared__ __align__(128) char smem[];

// ---------------------------------------------------------------- main kernel
__global__ __launch_bounds__(256, 2)
void vq_mma_kernel(const float* __restrict__ z,
                   const float* __restrict__ cb,
                   float* __restrict__ out) {
    const uint32_t sbase = (uint32_t)__cvta_generic_to_shared(smem);
    const int tid  = threadIdx.x;
    const int wid  = tid >> 5;
    const int lane = tid & 31;
    const int wr   = wid & 3;       // row group: 4 x 32 rows
    const int wc   = wid >> 2;      // code group: 2 x 64 codes
    const long long row0 = (long long)blockIdx.x * BM;

    if (tid < K_CODES) *(float*)(smem + SM_CSQ + tid * 4) = g_csq[tid];

    const float* zg = z + row0 * D_DIM;

    float acc[2][8][4];             // [m-tile][n-tile][frag]
    #pragma unroll
    for (int mt = 0; mt < 2; ++mt)
        #pragma unroll
        for (int nt = 0; nt < 8; ++nt)
            #pragma unroll
            for (int q = 0; q < 4; ++q) acc[mt][nt][q] = 0.f;

    // ldmatrix lane->address geometry (byte offsets within tile)
    const uint32_t a_off = (uint32_t)((wr * 32 + (lane & 15)) * ST + ((lane >> 4) * 8) * 2);
    const uint32_t b_off = (uint32_t)((wc * 64 + ((lane >> 4) << 3) + (lane & 7)) * ST
                                      + (((lane >> 3) & 1) * 8) * 2);

    // z load/convert geometry: 16 threads per row, 4 floats each
    const int lr0 = tid >> 4;        // +16 per iter (8 iters -> 128 rows)
    const int lkq = (tid & 15) * 4;  // 0,4,...,60
    // cb copy geometry: 8 uint4 per row
    const int cr  = tid >> 1;        // +128 per iter? no: idx>>3 below

    for (int ch = 0; ch < NCH; ++ch) {
        __syncthreads();             // tiles free (prev chunk's mma done)
        const int gk = ch * KC + lkq;
        const bool tail = (gk == 508);

        // ---- z tile: load fp32, pairwise split to bf16 hi/lo
        #pragma unroll
        for (int it = 0; it < 8; ++it) {
            const int r = lr0 + it * 16;
            const uint32_t so = (uint32_t)(r * ST + lkq * 2);
            const float* p = zg + (long long)r * D_DIM + gk;
            float2 a = *(const float2*)p;
            float2 b = tail ? make_float2(0.f, 0.f) : *(const float2*)(p + 2);
            __nv_bfloat162 h01 = __float22bfloat162_rn(a);
            __nv_bfloat162 h23 = __float22bfloat162_rn(b);
            float2 hf01 = __bfloat1622float2(h01);
            float2 hf23 = __bfloat1622float2(h23);
            __nv_bfloat162 l01 = __float22bfloat162_rn(
                make_float2(a.x - hf01.x, a.y - hf01.y));
            __nv_bfloat162 l23 = __float22bfloat162_rn(
                make_float2(b.x - hf23.x, b.y - hf23.y));
            *(uint2*)(smem + SM_ZH + so) = make_uint2(bits2(h01), bits2(h23));
            *(uint2*)(smem + SM_ZL + so) = make_uint2(bits2(l01), bits2(l23));
        }
        // ---- cb tile: straight bf16 copy from pre-split global (L2-hot)
        #pragma unroll
        for (int it = 0; it < 4; ++it) {
            const int idx = it * 256 + tid;   // 0..1023
            const int r = idx >> 3;           // code row 0..127
            const int q = idx & 7;            // uint4 slot within 128B
            const int gidx = r * 512 + ch * KC;
            uint4 vh = *((const uint4*)(g_cbh + gidx) + q);
            uint4 vl = *((const uint4*)(g_cbl + gidx) + q);
            *(uint4*)(smem + SM_CH + r * ST + q * 16) = vh;
            *(uint4*)(smem + SM_CL + r * ST + q * 16) = vl;
        }
        __syncthreads();

        // ---- mma over 4 k-steps of 16
        #pragma unroll
        for (int ks = 0; ks < 4; ++ks) {
            const uint32_t kb = (uint32_t)(ks * 32);   // 16 bf16 = 32 bytes
            uint32_t ah[2][4], al[2][4];
            #pragma unroll
            for (int mt = 0; mt < 2; ++mt) {
                const uint32_t ao = a_off + (uint32_t)(mt * 16 * ST) + kb;
                ldm4(ah[mt], sbase + SM_ZH + ao);
                ldm4(al[mt], sbase + SM_ZL + ao);
            }
            #pragma unroll
            for (int np = 0; np < 4; ++np) {           // n-tile pairs
                const uint32_t bo = b_off + (uint32_t)(np * 16 * ST) + kb;
                uint32_t bh[4], bl[4];
                ldm4(bh, sbase + SM_CH + bo);
                ldm4(bl, sbase + SM_CL + bo);
                #pragma unroll
                for (int mt = 0; mt < 2; ++mt) {
                    mma16816(acc[mt][np*2+0], ah[mt], bh + 0);
                    mma16816(acc[mt][np*2+1], ah[mt], bh + 2);
                    mma16816(acc[mt][np*2+0], ah[mt], bl + 0);
                    mma16816(acc[mt][np*2+1], ah[mt], bl + 2);
                    mma16816(acc[mt][np*2+0], al[mt], bh + 0);
                    mma16816(acc[mt][np*2+1], al[mt], bh + 2);
                }
            }
        }
    }

    // ---- epilogue: top-2 per row
    const float* csq_s = (const float*)(smem + SM_CSQ);
    float* bvp = (float*)(smem + SM_BV);
    float* svp = (float*)(smem + SM_SV);
    int*   bkp = (int*)(smem + SM_BK);

    #pragma unroll
    for (int mt = 0; mt < 2; ++mt) {
        #pragma unroll
        for (int rh = 0; rh < 2; ++rh) {
            float bv = 3.4e38f, sv = 3.4e38f;
            int bk = 0;
            #pragma unroll
            for (int nt = 0; nt < 8; ++nt) {
                #pragma unroll
                for (int s = 0; s < 2; ++s) {
                    const int c = wc * 64 + nt * 8 + (lane & 3) * 2 + s;
                    const float d2 = fmaf(-2.f, acc[mt][nt][rh * 2 + s], csq_s[c]);
                    if (d2 < bv) { sv = bv; bv = d2; bk = c; }
                    else if (d2 < sv) sv = d2;
                }
            }
            #pragma unroll
            for (int off = 1; off <= 2; off <<= 1) {
                float obv = __shfl_xor_sync(0xffffffffu, bv, off);
                float osv = __shfl_xor_sync(0xffffffffu, sv, off);
                int   obk = __shfl_xor_sync(0xffffffffu, bk, off);
                merge2(bv, sv, bk, obv, osv, obk);
            }
            if ((lane & 3) == 0) {
                const int r = wr * 32 + mt * 16 + rh * 8 + (lane >> 2);
                bvp[wc * 128 + r] = bv;
                svp[wc * 128 + r] = sv;
                bkp[wc * 128 + r] = bk;
            }
        }
    }
    __syncthreads();

    if (tid < BM) {
        float bv = bvp[tid], sv = svp[tid];
        int bk = bkp[tid];
        merge2(bv, sv, bk, bvp[128 + tid], svp[128 + tid], bkp[128 + tid]);
        *(int*)(smem + SM_KF + tid * 4) = bk;
        g_flag[row0 + tid] = ((sv - bv) < TAU) ? 1 : 0;
    }
    __syncthreads();

    // ---- gather: out[row] = codebook[kfin[row]]
    if (tid < 255) {
        const int dpos = tid * 2;
        float* ob = out + row0 * D_DIM + dpos;
        #pragma unroll 4
        for (int r = 0; r < BM; ++r) {
            int k = *(const int*)(smem + SM_KF + r * 4);
            float2 v = *(const float2*)(cb + k * D_DIM + dpos);
            *(float2*)(ob + (long long)r * D_DIM) = v;
        }
    }
}

// ---------------------------------------------------------------- exact refinement
__global__ __launch_bounds__(256)
void refine_kernel(const float* __restrict__ z,
                   const float* __restrict__ cb,
                   float* __restrict__ out) {
    const int tid = threadIdx.x, wid = tid >> 5, lane = tid & 31;
    const long long row0 = (long long)blockIdx.x * BM;
    for (int j = 0; j < 16; ++j) {
        const long long row = row0 + wid * 16 + j;
        if (!g_flag[row]) continue;                 // warp-uniform
        const float* zr = z + row * D_DIM;
        float zreg[16];
        #pragma unroll
        for (int t = 0; t < 16; ++t) {
            int d = lane + t * 32;
            zreg[t] = (d < D_DIM) ? zr[d] : 0.f;
        }
        float bv = 3.4e38f;
        int bk = 0;
        for (int c = 0; c < K_CODES; ++c) {
            const float* cr = cb + c * D_DIM;
            float s = 0.f;
            #pragma unroll
            for (int t = 0; t < 16; ++t) {
                int d = lane + t * 32;
                float cv = (d < D_DIM) ? cr[d] : 0.f;
                s = fmaf(zreg[t], cv, s);
            }
            #pragma unroll
            for (int off = 16; off; off >>= 1)
                s += __shfl_xor_sync(0xffffffffu, s, off);
            float d2 = fmaf(-2.f, s, g_csq[c]);
            if (d2 < bv) { bv = d2; bk = c; }       // strict < : lowest index wins ties
        }
        for (int d = lane; d < D_DIM; d += 32)
            out[row * D_DIM + d] = cb[bk * D_DIM + d];
    }
}

// ---------------------------------------------------------------- launch
extern "C" void kernel_launch(void* const* d_in, const int* in_sizes, int n_in,
                              void* d_out, int out_size) {
    const float* z  = (const float*)d_in[0];
    const float* cb = (const float*)d_in[1];
    float* out = (float*)d_out;

    cudaFuncSetAttribute(vq_mma_kernel, cudaFuncAttributeMaxDynamicSharedMemorySize,
                         SMEM_BYTES);

    const int n_rows  = in_sizes[0] / D_DIM;   // 131072
    const int nblocks = n_rows / BM;           // 1024

    prep_kernel<<<K_CODES, 256>>>(cb);
    vq_mma_kernel<<<nblocks, 256, SMEM_BYTES>>>(z, cb, out);
    refine_kernel<<<nblocks, 256>>>(z, cb, out);
}

// round 10
// speedup vs baseline: 1.5709x; 1.5709x over previous
#include <cuda_runtime.h>
#include <cuda_bf16.h>
#include <cstdint>

// VQ lookup via warp-level bf16 mma.sync (HMMA) + fused exact fp32 refinement.
//   dot(z,c) ~= zh*ch + zh*cl + zl*ch   (2-way bf16 Dekker split, 3 passes)
//   d2 = c_sq - 2*dot ; top-2 tracked ; gap < TAU -> exact fp32 re-argmin inline.
// R9: bisect from R7(344us): ONLY change = codebook pre-split to global bf16
// hi/lo (uint4 copy into smem, no per-chunk convert) + refine fused into epilogue.

#define D_DIM   510
#define K_CODES 128
#define BM      128
#define KC      64           // K-chunk (elements)
#define NCH     8            // 8*64 = 512, cols 510/511 zeroed
#define TAU     0.01f
#define ST      144          // smem tile row stride BYTES (72 bf16)

// smem byte offsets
#define SM_CSQ  0                        // 128 f32
#define SM_KF   512                      // 128 i32
#define SM_FLG  1024                     // 128 i32
#define SM_BV   1536                     // 2*128 f32
#define SM_SV   2560                     // 2*128 f32
#define SM_BK   3584                     // 2*128 i32
#define SM_ZH   4608
#define SM_ZL   (SM_ZH + 128*ST)
#define SM_CH   (SM_ZL + 128*ST)
#define SM_CL   (SM_CH + 128*ST)
#define SMEM_BYTES (SM_CL + 128*ST)      // 78336

__device__ float g_csq[K_CODES];
__device__ __align__(128) __nv_bfloat16 g_cbh[K_CODES * 512];  // 512-padded rows
__device__ __align__(128) __nv_bfloat16 g_cbl[K_CODES * 512];

// ---------------------------------------------------------------- prep: c_sq + cb split
__global__ void prep_kernel(const float* __restrict__ cb) {
    int k = blockIdx.x, tid = threadIdx.x;
    float s = 0.f;
    for (int d = tid; d < 512; d += 256) {
        float v = (d < D_DIM) ? cb[k * D_DIM + d] : 0.f;
        __nv_bfloat16 h = __float2bfloat16(v);
        __nv_bfloat16 l = __float2bfloat16(v - __bfloat162float(h));
        g_cbh[k * 512 + d] = h;
        g_cbl[k * 512 + d] = l;
        s = fmaf(v, v, s);
    }
    #pragma unroll
    for (int off = 16; off; off >>= 1) s += __shfl_xor_sync(0xffffffffu, s, off);
    __shared__ float red[8];
    if ((tid & 31) == 0) red[tid >> 5] = s;
    __syncthreads();
    if (tid == 0) {
        float t = 0.f;
        #pragma unroll
        for (int i = 0; i < 8; i++) t += red[i];
        g_csq[k] = t;
    }
}

// ---------------------------------------------------------------- helpers
__device__ __forceinline__ void split2(float x, __nv_bfloat16& h, __nv_bfloat16& l) {
    h = __float2bfloat16(x);
    l = __float2bfloat16(x - __bfloat162float(h));
}
__device__ __forceinline__ uint32_t pack2(__nv_bfloat16 a, __nv_bfloat16 b) {
    return (uint32_t)__bfloat16_as_ushort(b) << 16 | (uint32_t)__bfloat16_as_ushort(a);
}

__device__ __forceinline__ void ldm4(uint32_t* r, uint32_t addr) {
    asm volatile("ldmatrix.sync.aligned.m8n8.x4.shared.b16 {%0,%1,%2,%3}, [%4];"
                 : "=r"(r[0]), "=r"(r[1]), "=r"(r[2]), "=r"(r[3]) : "r"(addr));
}
__device__ __forceinline__ void mma16816(float* d, const uint32_t* a,
                                         const uint32_t* b) {
    asm volatile(
        "mma.sync.aligned.m16n8k16.row.col.f32.bf16.bf16.f32 "
        "{%0,%1,%2,%3}, {%4,%5,%6,%7}, {%8,%9}, {%0,%1,%2,%3};"
        : "+f"(d[0]), "+f"(d[1]), "+f"(d[2]), "+f"(d[3])
        : "r"(a[0]), "r"(a[1]), "r"(a[2]), "r"(a[3]), "r"(b[0]), "r"(b[1]));
}

__device__ __forceinline__ void merge2(float& bv, float& sv, int& bk,
                                       float obv, float osv, int obk) {
    if (obv < bv) { sv = fminf(bv, osv); bv = obv; bk = obk; }
    else          { sv = fminf(sv, obv); }
}

extern __shared__ __align__(128) char smem[];

// ---------------------------------------------------------------- main kernel
__global__ __launch_bounds__(256, 2)
void vq_mma_kernel(const float* __restrict__ z,
                   const float* __restrict__ cb,
                   float* __restrict__ out) {
    const uint32_t sbase = (uint32_t)__cvta_generic_to_shared(smem);
    const int tid  = threadIdx.x;
    const int wid  = tid >> 5;
    const int lane = tid & 31;
    const int wr   = wid & 3;       // row group: 4 x 32 rows
    const int wc   = wid >> 2;      // code group: 2 x 64 codes
    const long long row0 = (long long)blockIdx.x * BM;

    if (tid < K_CODES) *(float*)(smem + SM_CSQ + tid * 4) = g_csq[tid];

    const float* zg = z + row0 * D_DIM;

    float acc[2][8][4];             // [m-tile][n-tile][frag]
    #pragma unroll
    for (int mt = 0; mt < 2; ++mt)
        #pragma unroll
        for (int nt = 0; nt < 8; ++nt)
            #pragma unroll
            for (int q = 0; q < 4; ++q) acc[mt][nt][q] = 0.f;

    // ldmatrix lane->address geometry (byte offsets within tile)
    const uint32_t a_off = (uint32_t)((wr * 32 + (lane & 15)) * ST + ((lane >> 4) * 8) * 2);
    const uint32_t b_off = (uint32_t)((wc * 64 + ((lane >> 4) << 3) + (lane & 7)) * ST
                                      + (((lane >> 3) & 1) * 8) * 2);

    // z load/convert geometry: 16 threads per row, 4 floats each
    const int lr0 = tid >> 4;        // +16 per iter (8 iters -> 128 rows)
    const int lkq = (tid & 15) * 4;  // 0,4,...,60

    for (int ch = 0; ch < NCH; ++ch) {
        __syncthreads();             // tiles free (prev chunk's mma done)
        const int gk = ch * KC + lkq;
        const bool tail = (gk == 508);

        // ---- z tile: load fp32, scalar split to bf16 hi/lo (R7-proven path)
        #pragma unroll
        for (int it = 0; it < 8; ++it) {
            const int r = lr0 + it * 16;
            const uint32_t so = (uint32_t)(r * ST + lkq * 2);
            const float* p = zg + (long long)r * D_DIM + gk;
            float2 a = *(const float2*)p;
            float2 b = tail ? make_float2(0.f, 0.f) : *(const float2*)(p + 2);
            __nv_bfloat16 h0,l0,h1,l1,h2,l2,h3,l3;
            split2(a.x,h0,l0); split2(a.y,h1,l1);
            split2(b.x,h2,l2); split2(b.y,h3,l3);
            *(uint2*)(smem + SM_ZH + so) = make_uint2(pack2(h0,h1), pack2(h2,h3));
            *(uint2*)(smem + SM_ZL + so) = make_uint2(pack2(l0,l1), pack2(l2,l3));
        }
        // ---- cb tile: straight uint4 copy from pre-split global (L2-hot)
        #pragma unroll
        for (int it = 0; it < 4; ++it) {
            const int idx = it * 256 + tid;   // 0..1023
            const int r = idx >> 3;           // code row 0..127
            const int q = idx & 7;            // uint4 slot within 128B
            const int gidx = r * 512 + ch * KC;
            uint4 vh = *((const uint4*)(g_cbh + gidx) + q);
            uint4 vl = *((const uint4*)(g_cbl + gidx) + q);
            *(uint4*)(smem + SM_CH + r * ST + q * 16) = vh;
            *(uint4*)(smem + SM_CL + r * ST + q * 16) = vl;
        }
        __syncthreads();

        // ---- mma over 4 k-steps of 16
        #pragma unroll
        for (int ks = 0; ks < 4; ++ks) {
            const uint32_t kb = (uint32_t)(ks * 32);   // 16 bf16 = 32 bytes
            uint32_t ah[2][4], al[2][4];
            #pragma unroll
            for (int mt = 0; mt < 2; ++mt) {
                const uint32_t ao = a_off + (uint32_t)(mt * 16 * ST) + kb;
                ldm4(ah[mt], sbase + SM_ZH + ao);
                ldm4(al[mt], sbase + SM_ZL + ao);
            }
            #pragma unroll
            for (int np = 0; np < 4; ++np) {           // n-tile pairs
                const uint32_t bo = b_off + (uint32_t)(np * 16 * ST) + kb;
                uint32_t bh[4], bl[4];
                ldm4(bh, sbase + SM_CH + bo);
                ldm4(bl, sbase + SM_CL + bo);
                #pragma unroll
                for (int mt = 0; mt < 2; ++mt) {
                    mma16816(acc[mt][np*2+0], ah[mt], bh + 0);
                    mma16816(acc[mt][np*2+1], ah[mt], bh + 2);
                    mma16816(acc[mt][np*2+0], ah[mt], bl + 0);
                    mma16816(acc[mt][np*2+1], ah[mt], bl + 2);
                    mma16816(acc[mt][np*2+0], al[mt], bh + 0);
                    mma16816(acc[mt][np*2+1], al[mt], bh + 2);
                }
            }
        }
    }

    // ---- epilogue: top-2 per row
    const float* csq_s = (const float*)(smem + SM_CSQ);
    float* bvp = (float*)(smem + SM_BV);
    float* svp = (float*)(smem + SM_SV);
    int*   bkp = (int*)(smem + SM_BK);
    int*   flg = (int*)(smem + SM_FLG);

    #pragma unroll
    for (int mt = 0; mt < 2; ++mt) {
        #pragma unroll
        for (int rh = 0; rh < 2; ++rh) {
            float bv = 3.4e38f, sv = 3.4e38f;
            int bk = 0;
            #pragma unroll
            for (int nt = 0; nt < 8; ++nt) {
                #pragma unroll
                for (int s = 0; s < 2; ++s) {
                    const int c = wc * 64 + nt * 8 + (lane & 3) * 2 + s;
                    const float d2 = fmaf(-2.f, acc[mt][nt][rh * 2 + s], csq_s[c]);
                    if (d2 < bv) { sv = bv; bv = d2; bk = c; }
                    else if (d2 < sv) sv = d2;
                }
            }
            #pragma unroll
            for (int off = 1; off <= 2; off <<= 1) {
                float obv = __shfl_xor_sync(0xffffffffu, bv, off);
                float osv = __shfl_xor_sync(0xffffffffu, sv, off);
                int   obk = __shfl_xor_sync(0xffffffffu, bk, off);
                merge2(bv, sv, bk, obv, osv, obk);
            }
            if ((lane & 3) == 0) {
                const int r = wr * 32 + mt * 16 + rh * 8 + (lane >> 2);
                bvp[wc * 128 + r] = bv;
                svp[wc * 128 + r] = sv;
                bkp[wc * 128 + r] = bk;
            }
        }
    }
    __syncthreads();

    if (tid < BM) {
        float bv = bvp[tid], sv = svp[tid];
        int bk = bkp[tid];
        merge2(bv, sv, bk, bvp[128 + tid], svp[128 + tid], bkp[128 + tid]);
        *(int*)(smem + SM_KF + tid * 4) = bk;
        flg[tid] = ((sv - bv) < TAU) ? 1 : 0;
    }
    __syncthreads();

    // ---- gather: out[row] = codebook[kfin[row]]
    if (tid < 255) {
        const int dpos = tid * 2;
        float* ob = out + row0 * D_DIM + dpos;
        #pragma unroll 4
        for (int r = 0; r < BM; ++r) {
            int k = *(const int*)(smem + SM_KF + r * 4);
            float2 v = *(const float2*)(cb + k * D_DIM + dpos);
            *(float2*)(ob + (long long)r * D_DIM) = v;
        }
    }
    __syncthreads();

    // ---- fused exact refinement of near-tie rows (expected ~0.06 rows/CTA)
    for (int r = wid; r < BM; r += 8) {
        if (!flg[r]) continue;                      // warp-uniform branch
        const long long row = row0 + r;
        const float* zr = z + row * D_DIM;
        float zreg[16];
        #pragma unroll
        for (int t = 0; t < 16; ++t) {
            int d = lane + t * 32;
            zreg[t] = (d < D_DIM) ? zr[d] : 0.f;
        }
        float bv = 3.4e38f;
        int bk = 0;
        for (int c = 0; c < K_CODES; ++c) {
            const float* cr = cb + c * D_DIM;
            float s = 0.f;
            #pragma unroll
            for (int t = 0; t < 16; ++t) {
                int d = lane + t * 32;
                float cv = (d < D_DIM) ? cr[d] : 0.f;
                s = fmaf(zreg[t], cv, s);
            }
            #pragma unroll
            for (int off = 16; off; off >>= 1)
                s += __shfl_xor_sync(0xffffffffu, s, off);
            float d2 = fmaf(-2.f, s, csq_s[c]);
            if (d2 < bv) { bv = d2; bk = c; }       // strict <: lowest index wins ties
        }
        for (int d = lane; d < D_DIM; d += 32)
            out[row * D_DIM + d] = cb[bk * D_DIM + d];
    }
}

// ---------------------------------------------------------------- launch
extern "C" void kernel_launch(void* const* d_in, const int* in_sizes, int n_in,
                              void* d_out, int out_size) {
    const float* z  = (const float*)d_in[0];
    const float* cb = (const float*)d_in[1];
    float* out = (float*)d_out;

    cudaFuncSetAttribute(vq_mma_kernel, cudaFuncAttributeMaxDynamicSharedMemorySize,
                         SMEM_BYTES);

    const int n_rows  = in_sizes[0] / D_DIM;   // 131072
    const int nblocks = n_rows / BM;           // 1024

    prep_kernel<<<K_CODES, 256>>>(cb);
    vq_mma_kernel<<<nblocks, 256, SMEM_BYTES>>>(z, cb, out);
}